// round 1
// baseline (speedup 1.0000x reference)
#include <cuda_runtime.h>
#include <math.h>

#define NN 50000
#define EE 800000
#define HS 256      // padded row stride (floats) -> 1KB rows, 128B-aligned chunks
#define KHOPS 20

// ---------------- scratch (device globals; no allocation) ----------------
__device__ float g_hA[NN * HS];
__device__ float g_hB[NN * HS];
__device__ float g_acc[NN * HS];
__device__ float g_deg[NN];
__device__ float g_dis[NN];
__device__ int   g_cnt[NN];
__device__ int   g_rowptr[NN + 1];
__device__ int   g_cursor[NN];
__device__ int   g_col[EE];
__device__ float g_val[EE];

// ---------------- setup kernels ----------------
__global__ void k_zero_nodes() {
    int i = blockIdx.x * blockDim.x + threadIdx.x;
    if (i < NN) { g_deg[i] = 0.f; g_cnt[i] = 0; }
}

__global__ void k_degcnt(const int* __restrict__ ei, const float* __restrict__ ew) {
    int e = blockIdx.x * blockDim.x + threadIdx.x;
    if (e < EE) {
        int d = ei[EE + e];
        atomicAdd(&g_deg[d], ew[e]);
        atomicAdd(&g_cnt[d], 1);
    }
}

__global__ void k_dis() {
    int i = blockIdx.x * blockDim.x + threadIdx.x;
    if (i < NN) {
        float d = g_deg[i];
        g_dis[i] = (d > 0.f) ? rsqrtf(d) : 0.f;
    }
}

// single-block exclusive scan of g_cnt -> g_rowptr, g_cursor
__global__ void k_scan() {
    __shared__ int sh[1024];
    int tid = threadIdx.x;
    const int per = (NN + 1023) / 1024;
    int beg = tid * per; if (beg > NN) beg = NN;
    int end = beg + per; if (end > NN) end = NN;
    int s = 0;
    for (int i = beg; i < end; ++i) s += g_cnt[i];
    sh[tid] = s;
    __syncthreads();
    for (int off = 1; off < 1024; off <<= 1) {
        int v = (tid >= off) ? sh[tid - off] : 0;
        __syncthreads();
        sh[tid] += v;
        __syncthreads();
    }
    int run = (tid > 0) ? sh[tid - 1] : 0;
    for (int i = beg; i < end; ++i) {
        g_rowptr[i] = run;
        g_cursor[i] = run;
        run += g_cnt[i];
    }
    if (tid == 1023) g_rowptr[NN] = sh[1023];
}

__global__ void k_scatter(const int* __restrict__ ei, const float* __restrict__ ew) {
    int e = blockIdx.x * blockDim.x + threadIdx.x;
    if (e < EE) {
        int s = ei[e];
        int d = ei[EE + e];
        int p = atomicAdd(&g_cursor[d], 1);
        g_col[p] = s;
        g_val[p] = g_dis[s] * ew[e] * g_dis[d];
    }
}

__global__ void k_seed(const float* __restrict__ x, float* __restrict__ h) {
    int i = blockIdx.x * blockDim.x + threadIdx.x;
    if (i < NN) h[i * HS] = x[i];
}

// ---------------- propagation: h_out = A_norm * h_in  (CSR by dst) ----------------
// one warp per node per 32-channel chunk
__global__ void k_prop(const float* __restrict__ hin, float* __restrict__ hout, int Cin) {
    int gw   = (blockIdx.x * blockDim.x + threadIdx.x) >> 5;
    if (gw >= NN) return;
    int lane = threadIdx.x & 31;
    int c    = blockIdx.y * 32 + lane;
    if (c >= Cin) return;
    int beg = g_rowptr[gw];
    int end = g_rowptr[gw + 1];
    float a = 0.f;
    for (int p = beg; p < end; ++p) {
        float v = g_val[p];
        int   s = g_col[p];
        a += v * __ldg(&hin[s * HS + c]);
    }
    hout[gw * HS + c] = a;
}

// ---------------- GEMM: ACC (+)= H[M x Cin, stride HS] @ W[Cin x Cout] (+ bias) ---
#define BM 64
#define BN 64
#define BK 16
__global__ void k_gemm(const float* __restrict__ H, const float* __restrict__ W,
                       const float* __restrict__ bias, float* __restrict__ ACC,
                       int M, int Cin, int Cout, int accmode) {
    __shared__ float As[BK][BM + 4];  // +4 pad keeps 16B alignment, reduces st conflicts
    __shared__ float Bs[BK][BN];
    int tid = threadIdx.x;           // 256 threads
    int m0 = blockIdx.x * BM;
    int n0 = blockIdx.y * BN;
    int tm = tid >> 4;               // 0..15
    int tn = tid & 15;               // 0..15
    float acc[4][4];
#pragma unroll
    for (int i = 0; i < 4; ++i)
#pragma unroll
        for (int j = 0; j < 4; ++j) acc[i][j] = 0.f;

    for (int k0 = 0; k0 < Cin; k0 += BK) {
        // load A tile: 64 rows x 16 k
        {
            int lk = tid & 15;
            int lm = tid >> 4;
#pragma unroll
            for (int r = 0; r < 4; ++r) {
                int m = lm + r * 16;
                int gm = m0 + m, gk = k0 + lk;
                float v = 0.f;
                if (gm < M && gk < Cin) v = __ldg(&H[gm * HS + gk]);
                As[lk][m] = v;
            }
        }
        // load B tile: 16 k x 64 n
        {
            int ln  = tid & 63;
            int lkb = tid >> 6;
#pragma unroll
            for (int r = 0; r < 4; ++r) {
                int k = lkb + r * 4;
                int gk = k0 + k, gn = n0 + ln;
                float v = 0.f;
                if (gk < Cin && gn < Cout) v = __ldg(&W[gk * Cout + gn]);
                Bs[k][ln] = v;
            }
        }
        __syncthreads();
#pragma unroll
        for (int kk = 0; kk < BK; ++kk) {
            float4 a4 = *(const float4*)&As[kk][tm * 4];
            float4 b4 = *(const float4*)&Bs[kk][tn * 4];
            float a[4] = {a4.x, a4.y, a4.z, a4.w};
            float b[4] = {b4.x, b4.y, b4.z, b4.w};
#pragma unroll
            for (int i = 0; i < 4; ++i)
#pragma unroll
                for (int j = 0; j < 4; ++j) acc[i][j] += a[i] * b[j];
        }
        __syncthreads();
    }
    // epilogue
#pragma unroll
    for (int i = 0; i < 4; ++i) {
        int gm = m0 + tm * 4 + i;
        if (gm >= M) continue;
#pragma unroll
        for (int j = 0; j < 4; ++j) {
            int gn = n0 + tn * 4 + j;
            if (gn >= Cout) continue;
            float r = acc[i][j];
            if (accmode) ACC[gm * HS + gn] += r;
            else         ACC[gm * HS + gn] = r + bias[gn];
        }
    }
}

// ---------------- activations ----------------
__global__ void k_relu(const float* __restrict__ acc, float* __restrict__ dst, int Cout) {
    int i = blockIdx.x * blockDim.x + threadIdx.x;
    if (i < NN * Cout) {
        int n = i / Cout, c = i % Cout;
        float v = acc[n * HS + c];
        dst[n * HS + c] = v > 0.f ? v : 0.f;
    }
}

__global__ void k_sigmoid(const float* __restrict__ acc, float* __restrict__ out) {
    int i = blockIdx.x * blockDim.x + threadIdx.x;
    if (i < NN) {
        float v = acc[i * HS];
        out[i] = 1.f / (1.f + expf(-v));
    }
}

// ---------------- host ----------------
static void launch_gemm(const float* H, const float* W, const float* bias, float* ACC,
                        int M, int Cin, int Cout, int accmode) {
    dim3 grid((M + BM - 1) / BM, (Cout + BN - 1) / BN);
    k_gemm<<<grid, 256>>>(H, W, bias, ACC, M, Cin, Cout, accmode);
}

extern "C" void kernel_launch(void* const* d_in, const int* in_sizes, int n_in,
                              void* d_out, int out_size) {
    const float* x  = (const float*)d_in[0];
    const int*   ei = (const int*)d_in[1];
    const float* ew = (const float*)d_in[2];
    const float* Wl[5];
    const float* bl[5];
    for (int l = 0; l < 5; ++l) {
        Wl[l] = (const float*)d_in[3 + 2 * l];
        bl[l] = (const float*)d_in[4 + 2 * l];
    }
    float* out = (float*)d_out;

    float *hA, *hB, *acc;
    cudaGetSymbolAddress((void**)&hA, g_hA);
    cudaGetSymbolAddress((void**)&hB, g_hB);
    cudaGetSymbolAddress((void**)&acc, g_acc);

    // build normalized CSR (by dst)
    k_zero_nodes<<<(NN + 255) / 256, 256>>>();
    k_degcnt<<<(EE + 255) / 256, 256>>>(ei, ew);
    k_dis<<<(NN + 255) / 256, 256>>>();
    k_scan<<<1, 1024>>>();
    k_scatter<<<(EE + 255) / 256, 256>>>(ei, ew);
    k_seed<<<(NN + 255) / 256, 256>>>(x, hA);

    const int dims[6] = {1, 60, 100, 200, 80, 1};
    float* cur = hA;
    float* nxt = hB;
    for (int l = 0; l < 5; ++l) {
        int Cin = dims[l], Cout = dims[l + 1];
        const float* W = Wl[l];
        const float* b = bl[l];
        // out0 = h @ W[0] + bias
        launch_gemm(cur, W, b, acc, NN, Cin, Cout, 0);
        for (int k = 1; k <= KHOPS; ++k) {
            dim3 pgrid((NN * 32 + 255) / 256, (Cin + 31) / 32);
            k_prop<<<pgrid, 256>>>(cur, nxt, Cin);
            launch_gemm(nxt, W + (size_t)k * Cin * Cout, nullptr, acc, NN, Cin, Cout, 1);
            float* t = cur; cur = nxt; nxt = t;
        }
        if (l < 4) {
            k_relu<<<(NN * Cout + 255) / 256, 256>>>(acc, hA, Cout);
            cur = hA; nxt = hB;
        } else {
            k_sigmoid<<<(NN + 255) / 256, 256>>>(acc, out);
        }
    }
}

// round 2
// speedup vs baseline: 1.6024x; 1.6024x over previous
#include <cuda_runtime.h>
#include <math.h>

#define NN 50000
#define EE 800000
#define KHOPS 20
#define RP 50176          // rows padded past NN so GEMM tiles can over-read safely
#define MAXS 224          // max row stride (floats) = pad32(200)

// ---------------- scratch (device globals; zero-initialized at load) ----------
__device__ float g_P0[RP * MAXS];
__device__ float g_P1[RP * MAXS];
__device__ float g_P2[RP * MAXS];
__device__ float g_ACC[RP * MAXS];
__device__ float  g_deg[NN];
__device__ float  g_dis[NN];
__device__ int    g_cnt[NN];
__device__ int    g_rowptr[NN + 1];
__device__ int    g_cursor[NN];
__device__ float2 g_cv[EE];     // packed (src-as-float-bits, norm)

// ---------------- CSR build ----------------
__global__ void k_zero_nodes() {
    int i = blockIdx.x * blockDim.x + threadIdx.x;
    if (i < NN) { g_deg[i] = 0.f; g_cnt[i] = 0; }
}
__global__ void k_degcnt(const int* __restrict__ ei, const float* __restrict__ ew) {
    int e = blockIdx.x * blockDim.x + threadIdx.x;
    if (e < EE) {
        int d = ei[EE + e];
        atomicAdd(&g_deg[d], ew[e]);
        atomicAdd(&g_cnt[d], 1);
    }
}
__global__ void k_dis() {
    int i = blockIdx.x * blockDim.x + threadIdx.x;
    if (i < NN) {
        float d = g_deg[i];
        g_dis[i] = (d > 0.f) ? rsqrtf(d) : 0.f;
    }
}
__global__ void k_scan() {
    __shared__ int sh[1024];
    int tid = threadIdx.x;
    const int per = (NN + 1023) / 1024;
    int beg = tid * per; if (beg > NN) beg = NN;
    int end = beg + per; if (end > NN) end = NN;
    int s = 0;
    for (int i = beg; i < end; ++i) s += g_cnt[i];
    sh[tid] = s;
    __syncthreads();
    for (int off = 1; off < 1024; off <<= 1) {
        int v = (tid >= off) ? sh[tid - off] : 0;
        __syncthreads();
        sh[tid] += v;
        __syncthreads();
    }
    int run = (tid > 0) ? sh[tid - 1] : 0;
    for (int i = beg; i < end; ++i) {
        g_rowptr[i] = run;
        g_cursor[i] = run;
        run += g_cnt[i];
    }
    if (tid == 1023) g_rowptr[NN] = sh[1023];
}
__global__ void k_scatter(const int* __restrict__ ei, const float* __restrict__ ew) {
    int e = blockIdx.x * blockDim.x + threadIdx.x;
    if (e < EE) {
        int s = ei[e];
        int d = ei[EE + e];
        int p = atomicAdd(&g_cursor[d], 1);
        float2 cv;
        cv.x = __int_as_float(s);
        cv.y = g_dis[s] * ew[e] * g_dis[d];
        g_cv[p] = cv;
    }
}

// ---------------- propagation: warp per node, CH 32-wide channel chunks -------
// stride == CH*32; padding channels are always zero so no guards needed.
template <int CH>
__global__ void __launch_bounds__(256) k_prop(const float* __restrict__ hin,
                                              float* __restrict__ hout) {
    int w = (blockIdx.x * 256 + threadIdx.x) >> 5;
    if (w >= NN) return;
    int lane = threadIdx.x & 31;
    int beg = g_rowptr[w], end = g_rowptr[w + 1];
    float acc[CH];
#pragma unroll
    for (int t = 0; t < CH; ++t) acc[t] = 0.f;
    const int S = CH * 32;
    int p = beg;
    for (; p + 2 <= end; p += 2) {
        float2 cv0 = __ldg(&g_cv[p]);
        float2 cv1 = __ldg(&g_cv[p + 1]);
        const float* r0 = hin + (size_t)__float_as_int(cv0.x) * S + lane;
        const float* r1 = hin + (size_t)__float_as_int(cv1.x) * S + lane;
#pragma unroll
        for (int t = 0; t < CH; ++t) acc[t] += cv0.y * __ldg(r0 + 32 * t);
#pragma unroll
        for (int t = 0; t < CH; ++t) acc[t] += cv1.y * __ldg(r1 + 32 * t);
    }
    if (p < end) {
        float2 cv = __ldg(&g_cv[p]);
        const float* r = hin + (size_t)__float_as_int(cv.x) * S + lane;
#pragma unroll
        for (int t = 0; t < CH; ++t) acc[t] += cv.y * __ldg(r + 32 * t);
    }
    float* o = hout + (size_t)w * S + lane;
#pragma unroll
    for (int t = 0; t < CH; ++t) o[32 * t] = acc[t];
}

// ---------------- GEMM: ACC(+)= H[NN x Cin, stride sH] @ W[Cin x Cout] --------
#define BM 128
#define BN 64
#define BK 16
__global__ void __launch_bounds__(256) k_gemm(const float* __restrict__ H, int sH, int Cin,
                                              const float* __restrict__ W, int Cout,
                                              float* __restrict__ ACC, int sA,
                                              const float* __restrict__ bias, int accum) {
    __shared__ float As[BK][BM + 4];
    __shared__ float Bs[BK][BN];
    int tid = threadIdx.x;
    int m0 = blockIdx.x * BM, n0 = blockIdx.y * BN;
    int tm = tid >> 4, tn = tid & 15;
    float acc[8][4];
#pragma unroll
    for (int i = 0; i < 8; ++i)
#pragma unroll
        for (int j = 0; j < 4; ++j) acc[i][j] = 0.f;

    for (int k0 = 0; k0 < Cin; k0 += BK) {
        {   // A tile: rows are padded with zeros, so vector over-read is safe
            int row = tid >> 2, kq = (tid & 3) * 4;
#pragma unroll
            for (int r = 0; r < 2; ++r) {
                int m = row + 64 * r;
                float4 v = *(const float4*)&H[(size_t)(m0 + m) * sH + k0 + kq];
                As[kq + 0][m] = v.x; As[kq + 1][m] = v.y;
                As[kq + 2][m] = v.z; As[kq + 3][m] = v.w;
            }
        }
        {   // B tile (guarded: W is exactly Cin x Cout)
            int n = tid & 63, kb = tid >> 6;
#pragma unroll
            for (int r = 0; r < 4; ++r) {
                int k = kb + 4 * r;
                int gk = k0 + k;
                Bs[k][n] = (gk < Cin && n0 + n < Cout)
                               ? __ldg(&W[(size_t)gk * Cout + n0 + n]) : 0.f;
            }
        }
        __syncthreads();
#pragma unroll
        for (int kk = 0; kk < BK; ++kk) {
            float4 a0 = *(const float4*)&As[kk][tm * 8];
            float4 a1 = *(const float4*)&As[kk][tm * 8 + 4];
            float4 b  = *(const float4*)&Bs[kk][tn * 4];
            float av[8] = {a0.x, a0.y, a0.z, a0.w, a1.x, a1.y, a1.z, a1.w};
            float bv[4] = {b.x, b.y, b.z, b.w};
#pragma unroll
            for (int i = 0; i < 8; ++i)
#pragma unroll
                for (int j = 0; j < 4; ++j) acc[i][j] += av[i] * bv[j];
        }
        __syncthreads();
    }
#pragma unroll
    for (int i = 0; i < 8; ++i) {
        int gm = m0 + tm * 8 + i;
        if (gm >= NN) continue;
#pragma unroll
        for (int j = 0; j < 4; ++j) {
            int gn = n0 + tn * 4 + j;
            if (gn >= Cout) continue;
            float r = acc[i][j];
            if (accum) r += ACC[(size_t)gm * sA + gn];
            if (bias)  r += bias[gn];
            ACC[(size_t)gm * sA + gn] = r;
        }
    }
}

// ---------------- layer 1 (Cin=1): fused scalar prop + rank-1 update ----------
__global__ void __launch_bounds__(256) k_l1_out0(const float* __restrict__ x,
                                                 const float* __restrict__ W0,
                                                 const float* __restrict__ b) {
    int w = (blockIdx.x * 256 + threadIdx.x) >> 5;
    if (w >= NN) return;
    int lane = threadIdx.x & 31;
    float xv = x[w];
    g_ACC[(size_t)w * 64 + lane] = xv * W0[lane] + b[lane];
    int c = lane + 32;
    if (c < 60) g_ACC[(size_t)w * 64 + c] = xv * W0[c] + b[c];
}
__global__ void __launch_bounds__(256) k_l1_step(const float* __restrict__ hold,
                                                 float* __restrict__ hnew,
                                                 const float* __restrict__ Wk) {
    int w = (blockIdx.x * 256 + threadIdx.x) >> 5;
    if (w >= NN) return;
    int lane = threadIdx.x & 31;
    int beg = g_rowptr[w], end = g_rowptr[w + 1];
    float s = 0.f;
    for (int p = beg + lane; p < end; p += 32) {
        float2 cv = __ldg(&g_cv[p]);
        s += cv.y * __ldg(&hold[__float_as_int(cv.x)]);
    }
#pragma unroll
    for (int o = 16; o; o >>= 1) s += __shfl_xor_sync(0xffffffffu, s, o);
    if (lane == 0) hnew[w] = s;
    g_ACC[(size_t)w * 64 + lane] += s * Wk[lane];
    int c = lane + 32;
    if (c < 60) g_ACC[(size_t)w * 64 + c] += s * Wk[c];
}

// ---------------- layer 5 (Cout=1): fused scalar Horner step + GEMV -----------
__global__ void __launch_bounds__(256) k_l5(const float* __restrict__ X,
                                            const float* __restrict__ Wk,
                                            const float* __restrict__ told,
                                            float* __restrict__ tnew, int first) {
    int w = (blockIdx.x * 256 + threadIdx.x) >> 5;
    if (w >= NN) return;
    int lane = threadIdx.x & 31;
    float s = 0.f;
    if (!first) {
        int beg = g_rowptr[w], end = g_rowptr[w + 1];
        for (int p = beg + lane; p < end; p += 32) {
            float2 cv = __ldg(&g_cv[p]);
            s += cv.y * __ldg(&told[__float_as_int(cv.x)]);
        }
    }
    const float* xr = X + (size_t)w * 96;
    s += xr[lane] * Wk[lane] + xr[lane + 32] * Wk[lane + 32];
    if (lane < 16) s += xr[lane + 64] * Wk[lane + 64];
#pragma unroll
    for (int o = 16; o; o >>= 1) s += __shfl_xor_sync(0xffffffffu, s, o);
    if (lane == 0) tnew[w] = s;
}

// ---------------- activations ----------------
__global__ void __launch_bounds__(256) k_relu(const float* __restrict__ src, int si,
                                              float* __restrict__ dst, int so, int C) {
    int w = (blockIdx.x * 256 + threadIdx.x) >> 5;
    if (w >= NN) return;
    int lane = threadIdx.x & 31;
    for (int c = lane; c < C; c += 32)
        dst[(size_t)w * so + c] = fmaxf(src[(size_t)w * si + c], 0.f);
}
__global__ void k_sigmoid(const float* __restrict__ t, const float* __restrict__ b,
                          float* __restrict__ out) {
    int i = blockIdx.x * blockDim.x + threadIdx.x;
    if (i < NN) out[i] = 1.f / (1.f + expf(-(t[i] + b[0])));
}

// ---------------- host ----------------
static inline void launch_gemm(const float* H, int sH, int Cin, const float* W, int Cout,
                               float* ACC, int sA, const float* bias, int accum) {
    dim3 grid((NN + BM - 1) / BM, (Cout + BN - 1) / BN);
    k_gemm<<<grid, 256>>>(H, sH, Cin, W, Cout, ACC, sA, bias, accum);
}

extern "C" void kernel_launch(void* const* d_in, const int* in_sizes, int n_in,
                              void* d_out, int out_size) {
    const float* x  = (const float*)d_in[0];
    const int*   ei = (const int*)d_in[1];
    const float* ew = (const float*)d_in[2];
    const float* Wl[5]; const float* bl[5];
    for (int l = 0; l < 5; ++l) {
        Wl[l] = (const float*)d_in[3 + 2 * l];
        bl[l] = (const float*)d_in[4 + 2 * l];
    }
    float* out = (float*)d_out;

    float *P0, *P1, *P2, *ACCB;
    cudaGetSymbolAddress((void**)&P0, g_P0);
    cudaGetSymbolAddress((void**)&P1, g_P1);
    cudaGetSymbolAddress((void**)&P2, g_P2);
    cudaGetSymbolAddress((void**)&ACCB, g_ACC);

    // CSR build
    k_zero_nodes<<<(NN + 255) / 256, 256>>>();
    k_degcnt<<<(EE + 255) / 256, 256>>>(ei, ew);
    k_dis<<<(NN + 255) / 256, 256>>>();
    k_scan<<<1, 1024>>>();
    k_scatter<<<(EE + 255) / 256, 256>>>(ei, ew);

    const int WG = (NN * 32 + 255) / 256;   // 6250 blocks, warp per node

    // ---- layer 1: Cin=1, Cout=60 (input-space, scalar prop, fused GEMV) ----
    k_l1_out0<<<WG, 256>>>(x, Wl[0], bl[0]);
    {
        const float* hold = x;
        float* hnew = P1;
        for (int k = 1; k <= KHOPS; ++k) {
            k_l1_step<<<WG, 256>>>(hold, hnew, Wl[0] + (size_t)k * 60);
            hold = hnew;
            hnew = (hnew == P1) ? P2 : P1;
        }
    }
    k_relu<<<WG, 256>>>(ACCB, 64, P0, 64, 60);

    // ---- layer 2: Cin=60 (CH=2, s=64), Cout=100 (sA=128), input-space ----
    launch_gemm(P0, 64, 60, Wl[1], 100, ACCB, 128, bl[1], 0);
    {
        float* cur = P0; float* nxt = P1;
        for (int k = 1; k <= KHOPS; ++k) {
            k_prop<2><<<WG, 256>>>(cur, nxt);
            launch_gemm(nxt, 64, 60, Wl[1] + (size_t)k * 6000, 100, ACCB, 128, 0, 1);
            float* t = cur; cur = nxt; nxt = t;
        }
    }
    k_relu<<<WG, 256>>>(ACCB, 128, P0, 128, 100);

    // ---- layer 3: Cin=100 (CH=4, s=128), Cout=200 (sA=224), input-space ----
    launch_gemm(P0, 128, 100, Wl[2], 200, ACCB, 224, bl[2], 0);
    {
        float* cur = P0; float* nxt = P1;
        for (int k = 1; k <= KHOPS; ++k) {
            k_prop<4><<<WG, 256>>>(cur, nxt);
            launch_gemm(nxt, 128, 100, Wl[2] + (size_t)k * 20000, 200, ACCB, 224, 0, 1);
            float* t = cur; cur = nxt; nxt = t;
        }
    }
    k_relu<<<WG, 256>>>(ACCB, 224, P0, 224, 200);

    // ---- layer 4: Cin=200, Cout=80 — Horner in OUTPUT space (CH=3, s=96) ----
    launch_gemm(P0, 224, 200, Wl[3] + (size_t)KHOPS * 16000, 80, P1, 96, 0, 0);
    {
        float* t = P1; float* o = P2;
        for (int k = KHOPS - 1; k >= 0; --k) {
            k_prop<3><<<WG, 256>>>(t, o);
            launch_gemm(P0, 224, 200, Wl[3] + (size_t)k * 16000, 80, o, 96,
                        (k == 0) ? bl[3] : 0, 1);
            float* tmp = t; t = o; o = tmp;
        }
        k_relu<<<WG, 256>>>(t, 96, P0, 96, 80);
    }

    // ---- layer 5: Cin=80, Cout=1 — Horner, fused scalar prop + GEMV ----
    {
        float* tA = P1; float* tB = P2;
        k_l5<<<WG, 256>>>(P0, Wl[4] + (size_t)KHOPS * 80, 0, tA, 1);
        for (int k = KHOPS - 1; k >= 0; --k) {
            k_l5<<<WG, 256>>>(P0, Wl[4] + (size_t)k * 80, tA, tB, 0);
            float* tmp = tA; tA = tB; tB = tmp;
        }
        k_sigmoid<<<(NN + 255) / 256, 256>>>(tA, bl[4], out);
    }
}